// round 7
// baseline (speedup 1.0000x reference)
#include <cuda_runtime.h>
#include <math.h>

#define NB 32
#define CCH 384
#define HWP 3136
#define MM 8
#define DD 768
#define EE 768   // 2*C

// ---------------- device scratch (no allocations allowed) ----------------
__device__ __align__(16) float g_WT[DD * EE];      // WT[d][e] = W[e][d]
__device__ __align__(16) float g_Kt[NB * CCH * MM]; // [n][c][k]
__device__ __align__(16) float g_Vt[NB * CCH * MM]; // [n][c][k]

// ---------------- kernel 1: transpose W (E x D) -> WT (D x E) ----------------
__global__ void k_transpose(const float* __restrict__ W) {
    __shared__ float tile[32][33];
    int x = blockIdx.x * 32 + threadIdx.x;   // d for read
    int y = blockIdx.y * 32 + threadIdx.y;   // e for read
#pragma unroll
    for (int i = 0; i < 32; i += 8)
        tile[threadIdx.y + i][threadIdx.x] = W[(size_t)(y + i) * DD + x];
    __syncthreads();
    int x2 = blockIdx.y * 32 + threadIdx.x;  // e for write
    int y2 = blockIdx.x * 32 + threadIdx.y;  // d for write
#pragma unroll
    for (int i = 0; i < 32; i += 8)
        g_WT[(size_t)(y2 + i) * EE + x2] = tile[threadIdx.x][threadIdx.y + i];
}

// ---------------- kernel 2: kv = clip(gf @ W^T + b, 0, 6) -> g_Kt / g_Vt ----
// CTA tile: 16 rows x 48 e-cols, 2x2 register blocking, K-chunks of 96.
#define KV_EB 48
#define KV_RB 16
#define KV_KC 96

__device__ __forceinline__ void kv_store(int row, int e, float v) {
    int n = row >> 3;
    int m = row & 7;
    if (e < CCH) g_Kt[((size_t)n * CCH + e) * MM + m] = v;
    else         g_Vt[((size_t)n * CCH + (e - CCH)) * MM + m] = v;
}

__global__ __launch_bounds__(192) void k_kv(const float* __restrict__ gf,
                                            const float* __restrict__ bias) {
    __shared__ float Wc[KV_KC][KV_EB];   // 18 KB
    __shared__ float Gc[KV_RB][KV_KC];   // 6 KB
    int t   = threadIdx.x;
    int eb0 = blockIdx.x * KV_EB;
    int rb0 = blockIdx.y * KV_RB;
    int ri  = t / 24;   // 0..7  -> row pair
    int ei  = t % 24;   // 0..23 -> e pair

    float a00 = 0.f, a01 = 0.f, a10 = 0.f, a11 = 0.f;

    for (int kc = 0; kc < DD; kc += KV_KC) {
        __syncthreads();
        // load W chunk (from pre-transposed WT): rows d, cols e — coalesced float4
#pragma unroll
        for (int q = 0; q < 6; q++) {
            int idx = t + q * 192;            // 0..1151 = 96*12
            int dd = idx / 12, jj = idx % 12;
            float4 v = *(const float4*)(g_WT + (size_t)(kc + dd) * EE + eb0 + jj * 4);
            *(float4*)(&Wc[dd][jj * 4]) = v;
        }
        // load gf chunk: 16 rows x 96 cols
#pragma unroll
        for (int q = 0; q < 2; q++) {
            int idx = t + q * 192;            // 0..383 = 16*24
            int rr = idx / 24, jj = idx % 24;
            float4 v = *(const float4*)(gf + (size_t)(rb0 + rr) * DD + kc + jj * 4);
            *(float4*)(&Gc[rr][jj * 4]) = v;
        }
        __syncthreads();
#pragma unroll 8
        for (int dd = 0; dd < KV_KC; dd++) {
            float2 w2 = *(const float2*)(&Wc[dd][ei * 2]);
            float g0 = Gc[2 * ri][dd];
            float g1 = Gc[2 * ri + 1][dd];
            a00 += g0 * w2.x; a01 += g0 * w2.y;
            a10 += g1 * w2.x; a11 += g1 * w2.y;
        }
    }

    int e0 = eb0 + 2 * ei;
    float b0 = bias[e0], b1 = bias[e0 + 1];
    float v00 = fminf(fmaxf(a00 + b0, 0.f), 6.f);
    float v01 = fminf(fmaxf(a01 + b1, 0.f), 6.f);
    float v10 = fminf(fmaxf(a10 + b0, 0.f), 6.f);
    float v11 = fminf(fmaxf(a11 + b1, 0.f), 6.f);
    int r0 = rb0 + 2 * ri;
    kv_store(r0,     e0,     v00);
    kv_store(r0,     e0 + 1, v01);
    kv_store(r0 + 1, e0,     v10);
    kv_store(r0 + 1, e0 + 1, v11);
}

// ---------------- kernel 3: fused attention + residual ----------------
// One CTA = one batch n, one tile of 128 pixels. x tile staged once in smem.
// smem map (floats):
//   xs   [49152]            : x tile, xs[c*128 + p]
//   Ks4  [3072]  (768 f4)   : K[c][k], as 2 float4 per channel
//   attn [1024]             : attn[p*8 + k]
//   Vs4 / sred [3072]       : score partials (pass A), then V (pass B) — overlaid
#define SM_XS    0
#define SM_KS    49152
#define SM_ATTN  (49152 + 3072)
#define SM_VS    (49152 + 3072 + 1024)
#define SM_TOTAL ((49152 + 3072 + 1024 + 3072) * 4)   // 225280 bytes

__global__ __launch_bounds__(512, 1) void k_main(const float* __restrict__ x,
                                                 float* __restrict__ out) {
    extern __shared__ float sm[];
    float*  xs   = sm + SM_XS;
    float4* Ks4  = (float4*)(sm + SM_KS);
    float*  attn = sm + SM_ATTN;
    float4* Vs4  = (float4*)(sm + SM_VS);
    float*  sred = sm + SM_VS;           // overlaid with Vs4

    int t    = threadIdx.x;
    int n    = blockIdx.y;
    int p0   = blockIdx.x * 128;
    int pvalid = HWP - p0; if (pvalid > 128) pvalid = 128;
    int j4valid = pvalid >> 2;           // valid float4 per channel row

    const float* xb = x + (size_t)n * CCH * HWP + p0;

    // ---- phase 1: load x tile, K to smem, V to registers ----
#pragma unroll
    for (int q = 0; q < 24; q++) {
        int idx = t + q * 512;           // 0..12287
        int c = idx >> 5, j = idx & 31;
        float4 v;
        if (j < j4valid) v = *(const float4*)(xb + (size_t)c * HWP + j * 4);
        else             v = make_float4(0.f, 0.f, 0.f, 0.f);
        ((float4*)xs)[idx] = v;
    }
    const float4* Kt4 = (const float4*)g_Kt + (size_t)n * (CCH * MM / 4);
    const float4* Vt4 = (const float4*)g_Vt + (size_t)n * (CCH * MM / 4);
    Ks4[t] = Kt4[t];
    if (t < 256) Ks4[t + 512] = Kt4[t + 512];
    float4 vr0 = Vt4[t];
    float4 vr1 = (t < 256) ? Vt4[t + 512] : make_float4(0.f, 0.f, 0.f, 0.f);
    __syncthreads();

    // ---- pass A: partial scores. thread = (pixel p, channel-part r) ----
    int p = t & 127;
    int r = t >> 7;                       // 0..3, warp-uniform
    float s0=0.f,s1=0.f,s2=0.f,s3=0.f,s4=0.f,s5=0.f,s6=0.f,s7=0.f;
    const float* xp = xs + p;
    int cbase = r * 96;
#pragma unroll 8
    for (int j = 0; j < 96; j++) {
        int c = cbase + j;
        float xv = xp[c << 7];
        float4 ka = Ks4[2 * c];
        float4 kb = Ks4[2 * c + 1];
        s0 += xv * ka.x; s1 += xv * ka.y; s2 += xv * ka.z; s3 += xv * ka.w;
        s4 += xv * kb.x; s5 += xv * kb.y; s6 += xv * kb.z; s7 += xv * kb.w;
    }
    if (r > 0) {
        float4* sp = (float4*)(sred + ((size_t)(r - 1) * 128 + p) * 8);
        sp[0] = make_float4(s0, s1, s2, s3);
        sp[1] = make_float4(s4, s5, s6, s7);
    }
    __syncthreads();

    // ---- softmax (r == 0 threads keep their partial in regs) ----
    if (r == 0) {
#pragma unroll
        for (int q = 0; q < 3; q++) {
            const float4* sp = (const float4*)(sred + ((size_t)q * 128 + p) * 8);
            float4 A = sp[0], B = sp[1];
            s0 += A.x; s1 += A.y; s2 += A.z; s3 += A.w;
            s4 += B.x; s5 += B.y; s6 += B.z; s7 += B.w;
        }
        float mx = fmaxf(fmaxf(fmaxf(s0, s1), fmaxf(s2, s3)),
                         fmaxf(fmaxf(s4, s5), fmaxf(s6, s7)));
        float e0 = __expf(s0 - mx), e1 = __expf(s1 - mx);
        float e2 = __expf(s2 - mx), e3 = __expf(s3 - mx);
        float e4 = __expf(s4 - mx), e5 = __expf(s5 - mx);
        float e6 = __expf(s6 - mx), e7 = __expf(s7 - mx);
        float inv = __fdividef(1.f, e0+e1+e2+e3+e4+e5+e6+e7);
        float4* ap = (float4*)(attn + p * 8);
        ap[0] = make_float4(e0 * inv, e1 * inv, e2 * inv, e3 * inv);
        ap[1] = make_float4(e4 * inv, e5 * inv, e6 * inv, e7 * inv);
    }
    __syncthreads();

    // ---- park V into smem (overlays sred, now dead) ----
    Vs4[t] = vr0;
    if (t < 256) Vs4[t + 512] = vr1;
    __syncthreads();

    // ---- pass B: out[c][p] = attn . V[c][:] + x[c][p] ----
    const float4* ap = (const float4*)(attn + p * 8);
    float4 A0 = ap[0], A1 = ap[1];
    float* op = out + (size_t)n * CCH * HWP + p0 + p;
    bool wr = p < pvalid;
    int cb = r;                           // channel offset 0..3
#pragma unroll 4
    for (int i = 0; i < 96; i++) {
        int c = cb + 4 * i;
        float4 va = Vs4[2 * c];
        float4 vb = Vs4[2 * c + 1];
        float acc = A0.x * va.x + A0.y * va.y + A0.z * va.z + A0.w * va.w
                  + A1.x * vb.x + A1.y * vb.y + A1.z * vb.z + A1.w * vb.w;
        if (wr) op[(size_t)c * HWP] = acc + xp[c << 7];
    }
}

// ---------------- launch ----------------
extern "C" void kernel_launch(void* const* d_in, const int* in_sizes, int n_in,
                              void* d_out, int out_size) {
    const float* x  = (const float*)d_in[0];
    const float* gf = (const float*)d_in[1];
    const float* W  = (const float*)d_in[2];
    const float* b  = (const float*)d_in[3];
    float* out = (float*)d_out;

    k_transpose<<<dim3(24, 24), dim3(32, 8)>>>(W);
    k_kv<<<dim3(EE / KV_EB, 256 / KV_RB), 192>>>(gf, b);

    cudaFuncSetAttribute(k_main, cudaFuncAttributeMaxDynamicSharedMemorySize, SM_TOTAL);
    k_main<<<dim3((HWP + 127) / 128, NB), 512, SM_TOTAL>>>(x, out);
}

// round 8
// speedup vs baseline: 1.2120x; 1.2120x over previous
#include <cuda_runtime.h>
#include <math.h>

#define NB 32
#define CCH 384
#define HWP 3136
#define MM 8
#define DD 768
#define EE 768   // 2*C

// ---------------- device scratch (no allocations allowed) ----------------
__device__ __align__(16) float g_WT[DD * EE];       // WT[d][e] = W[e][d]
__device__ __align__(16) float g_Kt[NB * CCH * MM]; // [n][c][k]
__device__ __align__(16) float g_Vt[NB * CCH * MM]; // [n][c][k]

// ---------------- kernel 1: transpose W (E x D) -> WT (D x E) ----------------
__global__ void k_transpose(const float* __restrict__ W) {
    __shared__ float tile[32][33];
    int x = blockIdx.x * 32 + threadIdx.x;   // d for read
    int y = blockIdx.y * 32 + threadIdx.y;   // e for read
#pragma unroll
    for (int i = 0; i < 32; i += 8)
        tile[threadIdx.y + i][threadIdx.x] = W[(size_t)(y + i) * DD + x];
    __syncthreads();
    int x2 = blockIdx.y * 32 + threadIdx.x;  // e for write
    int y2 = blockIdx.x * 32 + threadIdx.y;  // d for write
#pragma unroll
    for (int i = 0; i < 32; i += 8)
        g_WT[(size_t)(y2 + i) * EE + x2] = tile[threadIdx.x][threadIdx.y + i];
}

// ---------------- kernel 2: kv = clip(gf @ W^T + b, 0, 6) -> g_Kt / g_Vt ----
#define KV_EB 48
#define KV_RB 16
#define KV_KC 96

__device__ __forceinline__ void kv_store(int row, int e, float v) {
    int n = row >> 3;
    int m = row & 7;
    if (e < CCH) g_Kt[((size_t)n * CCH + e) * MM + m] = v;
    else         g_Vt[((size_t)n * CCH + (e - CCH)) * MM + m] = v;
}

__global__ __launch_bounds__(192) void k_kv(const float* __restrict__ gf,
                                            const float* __restrict__ bias) {
    __shared__ float Wc[KV_KC][KV_EB];   // 18 KB
    __shared__ float Gc[KV_RB][KV_KC];   // 6 KB
    int t   = threadIdx.x;
    int eb0 = blockIdx.x * KV_EB;
    int rb0 = blockIdx.y * KV_RB;
    int ri  = t / 24;   // 0..7  -> row pair
    int ei  = t % 24;   // 0..23 -> e pair

    float a00 = 0.f, a01 = 0.f, a10 = 0.f, a11 = 0.f;

    for (int kc = 0; kc < DD; kc += KV_KC) {
        __syncthreads();
#pragma unroll
        for (int q = 0; q < 6; q++) {
            int idx = t + q * 192;            // 0..1151 = 96*12
            int dd = idx / 12, jj = idx % 12;
            float4 v = *(const float4*)(g_WT + (size_t)(kc + dd) * EE + eb0 + jj * 4);
            *(float4*)(&Wc[dd][jj * 4]) = v;
        }
#pragma unroll
        for (int q = 0; q < 2; q++) {
            int idx = t + q * 192;            // 0..383 = 16*24
            int rr = idx / 24, jj = idx % 24;
            float4 v = *(const float4*)(gf + (size_t)(rb0 + rr) * DD + kc + jj * 4);
            *(float4*)(&Gc[rr][jj * 4]) = v;
        }
        __syncthreads();
#pragma unroll 8
        for (int dd = 0; dd < KV_KC; dd++) {
            float2 w2 = *(const float2*)(&Wc[dd][ei * 2]);
            float g0 = Gc[2 * ri][dd];
            float g1 = Gc[2 * ri + 1][dd];
            a00 += g0 * w2.x; a01 += g0 * w2.y;
            a10 += g1 * w2.x; a11 += g1 * w2.y;
        }
    }

    int e0 = eb0 + 2 * ei;
    float b0 = bias[e0], b1 = bias[e0 + 1];
    float v00 = fminf(fmaxf(a00 + b0, 0.f), 6.f);
    float v01 = fminf(fmaxf(a01 + b1, 0.f), 6.f);
    float v10 = fminf(fmaxf(a10 + b0, 0.f), 6.f);
    float v11 = fminf(fmaxf(a11 + b1, 0.f), 6.f);
    int r0 = rb0 + 2 * ri;
    kv_store(r0,     e0,     v00);
    kv_store(r0,     e0 + 1, v01);
    kv_store(r0 + 1, e0,     v10);
    kv_store(r0 + 1, e0 + 1, v11);
}

// ---------------- kernel 3: fused attention + residual (x in registers) ----
// Lane map: part r = lane>>3 (channel quarter, 96 ch), pixel = p0 + warp*8 + (lane&7).
// 64 pixels per CTA, 256 threads, 2 CTAs/SM.
// K/V smem: float4 pairs per channel, skewed 32B (2 float4) per 96-channel block
// so the 4 parts' broadcast loads hit disjoint bank groups:
//   f4 index(c, half) = 2c + 2*(c/96) + half ;  part base = r*194.
__global__ __launch_bounds__(256, 2) void k_attn(const float* __restrict__ x,
                                                 float* __restrict__ out) {
    __shared__ float4 Ks4[774];
    __shared__ float4 Vs4[774];

    int tid  = threadIdx.x;
    int n    = blockIdx.y;
    int lane = tid & 31;
    int warp = tid >> 5;
    int r    = lane >> 3;                       // 0..3
    int p    = blockIdx.x * 64 + warp * 8 + (lane & 7);

    const float4* Kt4 = (const float4*)g_Kt + (size_t)n * (CCH * MM / 4);
    const float4* Vt4 = (const float4*)g_Vt + (size_t)n * (CCH * MM / 4);
#pragma unroll
    for (int i = tid; i < 768; i += 256) {
        int c = i >> 1, half = i & 1;
        int dst = 2 * c + 2 * (c / 96) + half;
        Ks4[dst] = Kt4[i];
        Vs4[dst] = Vt4[i];
    }
    __syncthreads();

    // ---- pass 0: stream this lane's 96 x values into registers (read once) ----
    float xr[96];
    const float* xp = x + ((size_t)n * CCH + r * 96) * HWP + p;
#pragma unroll
    for (int j = 0; j < 96; j++)
        xr[j] = __ldcs(xp + (size_t)j * HWP);

    // ---- pass 1: partial scores over this part's 96 channels ----
    float s0=0.f,s1=0.f,s2=0.f,s3=0.f,s4=0.f,s5=0.f,s6=0.f,s7=0.f;
    int base = r * 194;
#pragma unroll
    for (int j = 0; j < 96; j++) {
        float xv = xr[j];
        float4 ka = Ks4[base + 2 * j];
        float4 kb = Ks4[base + 2 * j + 1];
        s0 += xv * ka.x; s1 += xv * ka.y; s2 += xv * ka.z; s3 += xv * ka.w;
        s4 += xv * kb.x; s5 += xv * kb.y; s6 += xv * kb.z; s7 += xv * kb.w;
    }

    // ---- reduce across the 4 parts (lanes l, l^8, l^16, l^24) ----
#define RED4(v) v += __shfl_xor_sync(0xffffffffu, v, 8); \
                v += __shfl_xor_sync(0xffffffffu, v, 16);
    RED4(s0) RED4(s1) RED4(s2) RED4(s3)
    RED4(s4) RED4(s5) RED4(s6) RED4(s7)
#undef RED4

    // ---- softmax over 8 heads (every lane computes it redundantly) ----
    float mx = fmaxf(fmaxf(fmaxf(s0, s1), fmaxf(s2, s3)),
                     fmaxf(fmaxf(s4, s5), fmaxf(s6, s7)));
    float e0 = __expf(s0 - mx), e1 = __expf(s1 - mx);
    float e2 = __expf(s2 - mx), e3 = __expf(s3 - mx);
    float e4 = __expf(s4 - mx), e5 = __expf(s5 - mx);
    float e6 = __expf(s6 - mx), e7 = __expf(s7 - mx);
    float inv = __fdividef(1.f, e0+e1+e2+e3+e4+e5+e6+e7);
    float a0 = e0*inv, a1 = e1*inv, a2 = e2*inv, a3 = e3*inv;
    float a4 = e4*inv, a5 = e5*inv, a6 = e6*inv, a7 = e7*inv;

    // ---- pass 2: out[c][p] = attn . V[c][:] + x[c][p]  (x from registers) ----
    float* op = out + ((size_t)n * CCH + r * 96) * HWP + p;
#pragma unroll
    for (int j = 0; j < 96; j++) {
        float4 va = Vs4[base + 2 * j];
        float4 vb = Vs4[base + 2 * j + 1];
        float acc = a0 * va.x + a1 * va.y + a2 * va.z + a3 * va.w
                  + a4 * vb.x + a5 * vb.y + a6 * vb.z + a7 * vb.w;
        __stcs(op + (size_t)j * HWP, acc + xr[j]);
    }
}

// ---------------- launch ----------------
extern "C" void kernel_launch(void* const* d_in, const int* in_sizes, int n_in,
                              void* d_out, int out_size) {
    const float* x  = (const float*)d_in[0];
    const float* gf = (const float*)d_in[1];
    const float* W  = (const float*)d_in[2];
    const float* b  = (const float*)d_in[3];
    float* out = (float*)d_out;

    k_transpose<<<dim3(24, 24), dim3(32, 8)>>>(W);
    k_kv<<<dim3(EE / KV_EB, 256 / KV_RB), 192>>>(gf, b);
    k_attn<<<dim3(HWP / 64, NB), 256>>>(x, out);
}